// round 4
// baseline (speedup 1.0000x reference)
#include <cuda_runtime.h>
#include <cstdint>
#include <math.h>

// ---- problem constants ----
#define BATCH    16
#define KTUP     16384
#define ADDS     32
#define NP       36          // 2^2 + 32 candidates per point
#define DIM      65536       // IN_DIM == OUT_DIM
#define HALF_B   8

// =====================================================================
// threefry-2x32, 20 rounds, exactly as jax._src.prng (key = (0, 42)).
// Partitionable mode: counter = (0, flat_index), bits = o0 ^ o1.
// =====================================================================
__device__ __forceinline__ void threefry2x32_42(uint32_t c0, uint32_t c1,
                                                uint32_t& o0, uint32_t& o1) {
    const uint32_t ks0 = 0u;
    const uint32_t ks1 = 42u;
    const uint32_t ks2 = 0x1BD11BDAu ^ 0u ^ 42u;
    uint32_t x0 = c0 + ks0;
    uint32_t x1 = c1 + ks1;
#define TF_R(rot) { x0 += x1; x1 = __funnelshift_l(x1, x1, rot); x1 ^= x0; }
    TF_R(13) TF_R(15) TF_R(26) TF_R(6)   x0 += ks1; x1 += ks2 + 1u;
    TF_R(17) TF_R(29) TF_R(16) TF_R(24)  x0 += ks2; x1 += ks0 + 2u;
    TF_R(13) TF_R(15) TF_R(26) TF_R(6)   x0 += ks0; x1 += ks1 + 3u;
    TF_R(17) TF_R(29) TF_R(16) TF_R(24)  x0 += ks1; x1 += ks2 + 4u;
    TF_R(13) TF_R(15) TF_R(26) TF_R(6)   x0 += ks2; x1 += ks0 + 5u;
#undef TF_R
    o0 = x0; o1 = x1;
}

__device__ __forceinline__ uint32_t jax_random_bits32(uint32_t e) {
    uint32_t o0, o1;
    threefry2x32_42(0u, e, o0, o1);
    return o0 ^ o1;
}

// bits -> uniform [0,1) -> *(1-1e-6) -> *65536 -> floor -> int32, bit-exact vs JAX
__device__ __forceinline__ int bits_to_idx(uint32_t bits) {
    float u = __uint_as_float((bits >> 9) | 0x3f800000u) - 1.0f;
    const float OME = (float)(1.0 - 1e-6);   // fl32(0.999999)
    float t = __fmul_rn(__fmul_rn(u, OME), 65536.0f);
    return (int)t;                           // trunc == floor, t >= 0
}

// =====================================================================
// XLA LogisticExpander form: logistic(x) = 1 / (1 + exp(-x)).
// exp = libdevice __nv_expf == CUDA accurate expf (no fast-math here).
// All surrounding ops rn, no contraction.
// =====================================================================
__device__ __forceinline__ float xla_sigmoid(float v) {
    float e = expf(-v);                      // accurate expf (libdevice)
    return __fdiv_rn(1.0f, __fadd_rn(1.0f, e));
}

// softplus (feeds sigma only; continuous path, fast version OK)
__device__ __forceinline__ float softplus_f(float v) {
    return fmaxf(v, 0.0f) + log1pf(__expf(-fabsf(v)));
}

// =====================================================================
// kernel 1: y[b, o] = bias[o]
// =====================================================================
__global__ __launch_bounds__(256) void hyper_init(const float* __restrict__ bias,
                                                  float* __restrict__ y) {
    int i = blockIdx.x * 256 + threadIdx.x;
    y[i] = __ldg(bias + (i & (DIM - 1)));
}

// =====================================================================
// kernel 2: one warp per (b_half, k); lane = sample index a (0..31).
// Each lane computes 4 partitionable-threefry hashes: (bh, r=0/1) and
// (bh+8, r=0/1). Lanes 0..3 also carry the 4 floor/ceil neighbors.
// =====================================================================
__global__ __launch_bounds__(256) void hyper_main(const float*  __restrict__ x,
                                                  const float4* __restrict__ res4,
                                                  float*        __restrict__ y) {
    const int w    = blockIdx.x * 8 + (threadIdx.x >> 5);   // 0 .. 131071
    const int lane = threadIdx.x & 31;
    const int bh   = w >> 14;            // 0..7
    const int k    = w & (KTUP - 1);

    // ---- per-batch params (redundant across lanes: free at warp level) ----
    float m0[2], m1[2], nh[2], val[2];
#pragma unroll
    for (int t = 0; t < 2; ++t) {
        const int b = bh + HALF_B * t;
        float4 r = __ldg(&res4[b * KTUP + k]);
        m0[t] = __fmul_rn(xla_sigmoid(r.x), 65535.0f);
        m1[t] = __fmul_rn(xla_sigmoid(r.y), 65535.0f);
        float sg = (softplus_f(r.z + 2.0f) + 1e-6f) * 65536.0f;
        nh[t]  = -0.5f / (sg * sg);
        val[t] = r.w;
    }

    // ---- sampled integer tuples: flat element index in (B,K,ADD,RANK) ----
    // e(b, k, a, r) = ((b*K + k)*ADD + a)*2 + r
    const uint32_t e00 = (uint32_t)(((bh * KTUP + k) * ADDS + lane) * 2);
    int si0[2], si1[2];
    si0[0] = bits_to_idx(jax_random_bits32(e00));                 // (bh,   dim0)
    si1[0] = bits_to_idx(jax_random_bits32(e00 + 1u));            // (bh,   dim1)
    si0[1] = bits_to_idx(jax_random_bits32(e00 + 0x800000u));     // (bh+8, dim0)
    si1[1] = bits_to_idx(jax_random_bits32(e00 + 0x800001u));     // (bh+8, dim1)

    // ---- Gaussian props (continuous path; fast math fine) ----
    float psamp[2];
#pragma unroll
    for (int t = 0; t < 2; ++t) {
        float d0 = (float)si0[t] - m0[t];
        float d1 = (float)si1[t] - m1[t];
        psamp[t] = __expf(fmaf(d0, d0, d1 * d1) * nh[t]);
    }

    float pnb[2] = {0.0f, 0.0f};
    int   ni0[2] = {0, 0}, ni1[2] = {0, 0};
    if (lane < 4) {
        // mask rows (T,T),(T,F),(F,T),(F,F); True->floor
#pragma unroll
        for (int t = 0; t < 2; ++t) {
            float f0 = floorf(m0[t]), c0 = ceilf(m0[t]);
            float f1 = floorf(m1[t]), c1 = ceilf(m1[t]);
            float g0 = (lane & 2) ? c0 : f0;
            float g1 = (lane & 1) ? c1 : f1;
            ni0[t] = (int)g0;  ni1[t] = (int)g1;
            float d0 = g0 - m0[t];
            float d1 = g1 - m1[t];
            pnb[t] = __expf(fmaf(d0, d0, d1 * d1) * nh[t]);
        }
    }

    // ---- normalization: den = sum_p props + P*eps ----
    float s0 = psamp[0] + pnb[0];
    float s1 = psamp[1] + pnb[1];
#pragma unroll
    for (int o = 16; o > 0; o >>= 1) {
        s0 += __shfl_xor_sync(0xffffffffu, s0, o);
        s1 += __shfl_xor_sync(0xffffffffu, s1, o);
    }
    const float sc0 = __fdividef(val[0], s0 + (float)(NP) * 1e-6f);
    const float sc1 = __fdividef(val[1], s1 + (float)(NP) * 1e-6f);

    // ---- gather / scatter-add ----
    const float* xr0 = x + (size_t)bh * DIM;
    const float* xr1 = x + (size_t)(bh + HALF_B) * DIM;
    float* yr0 = y + (size_t)bh * DIM;
    float* yr1 = y + (size_t)(bh + HALF_B) * DIM;

    atomicAdd(yr0 + si0[0], sc0 * psamp[0] * __ldg(xr0 + si1[0]));
    atomicAdd(yr1 + si0[1], sc1 * psamp[1] * __ldg(xr1 + si1[1]));
    if (lane < 4) {
        atomicAdd(yr0 + ni0[0], sc0 * pnb[0] * __ldg(xr0 + ni1[0]));
        atomicAdd(yr1 + ni0[1], sc1 * pnb[1] * __ldg(xr1 + ni1[1]));
    }
}

// =====================================================================
extern "C" void kernel_launch(void* const* d_in, const int* in_sizes, int n_in,
                              void* d_out, int out_size) {
    const float*  x    = (const float*)d_in[0];          // (16, 65536)
    const float4* res4 = (const float4*)d_in[1];         // (16, 16384, 4)
    const float*  bias = (const float*)d_in[2];          // (65536,)
    // d_in[3] = temp_indices: fully overwritten by learn_cols -> unused
    float* y = (float*)d_out;                            // (16, 65536)

    hyper_init<<<(BATCH * DIM) / 256, 256>>>(bias, y);
    hyper_main<<<(HALF_B * KTUP) / 8, 256>>>(x, res4, y);
}

// round 5
// speedup vs baseline: 1.1616x; 1.1616x over previous
#include <cuda_runtime.h>
#include <cstdint>
#include <math.h>

// ---- problem constants ----
#define BATCH    16
#define KTUP     16384
#define ADDS     32
#define NP       36          // 2^2 + 32 candidates per point
#define DIM      65536       // IN_DIM == OUT_DIM
#define HALF_B   8

// 4MB precomputed-parameter scratch: {m0, m1, nh, val} per (b, k)
__device__ float4 g_params[BATCH * KTUP];

// =====================================================================
// threefry-2x32, 20 rounds, exactly as jax._src.prng (key = (0, 42)).
// Partitionable mode: counter = (0, flat_index), bits = o0 ^ o1.
// =====================================================================
__device__ __forceinline__ void threefry2x32_42(uint32_t c0, uint32_t c1,
                                                uint32_t& o0, uint32_t& o1) {
    const uint32_t ks0 = 0u;
    const uint32_t ks1 = 42u;
    const uint32_t ks2 = 0x1BD11BDAu ^ 0u ^ 42u;
    uint32_t x0 = c0 + ks0;
    uint32_t x1 = c1 + ks1;
#define TF_R(rot) { x0 += x1; x1 = __funnelshift_l(x1, x1, rot); x1 ^= x0; }
    TF_R(13) TF_R(15) TF_R(26) TF_R(6)   x0 += ks1; x1 += ks2 + 1u;
    TF_R(17) TF_R(29) TF_R(16) TF_R(24)  x0 += ks2; x1 += ks0 + 2u;
    TF_R(13) TF_R(15) TF_R(26) TF_R(6)   x0 += ks0; x1 += ks1 + 3u;
    TF_R(17) TF_R(29) TF_R(16) TF_R(24)  x0 += ks1; x1 += ks2 + 4u;
    TF_R(13) TF_R(15) TF_R(26) TF_R(6)   x0 += ks2; x1 += ks0 + 5u;
#undef TF_R
    o0 = x0; o1 = x1;
}

__device__ __forceinline__ uint32_t jax_random_bits32(uint32_t e) {
    uint32_t o0, o1;
    threefry2x32_42(0u, e, o0, o1);
    return o0 ^ o1;
}

// bits -> uniform [0,1) -> *(1-1e-6) -> *65536 -> floor -> int32, bit-exact vs JAX
__device__ __forceinline__ int bits_to_idx(uint32_t bits) {
    float u = __uint_as_float((bits >> 9) | 0x3f800000u) - 1.0f;
    const float OME = (float)(1.0 - 1e-6);   // fl32(0.999999)
    float t = __fmul_rn(__fmul_rn(u, OME), 65536.0f);
    return (int)t;                           // trunc == floor, t >= 0
}

// ---- sigmoid / softplus: IDENTICAL arithmetic to the passing round-4 build ----
__device__ __forceinline__ float xla_sigmoid(float v) {
    float e = expf(-v);                      // accurate expf
    return __fdiv_rn(1.0f, __fadd_rn(1.0f, e));
}
__device__ __forceinline__ float softplus_f(float v) {
    return fmaxf(v, 0.0f) + log1pf(__expf(-fabsf(v)));
}

// =====================================================================
// kernel 0: per-(b,k) parameter precompute (runs once, ~4us)
// =====================================================================
__global__ __launch_bounds__(256) void hyper_params(const float4* __restrict__ res4) {
    int i = blockIdx.x * 256 + threadIdx.x;          // 0 .. BATCH*KTUP-1
    float4 r = __ldg(&res4[i]);
    float4 p;
    p.x = __fmul_rn(xla_sigmoid(r.x), 65535.0f);     // m0
    p.y = __fmul_rn(xla_sigmoid(r.y), 65535.0f);     // m1
    float sg = (softplus_f(r.z + 2.0f) + 1e-6f) * 65536.0f;
    p.z = -0.5f / (sg * sg);                         // nh
    p.w = r.w;                                       // val
    g_params[i] = p;
}

// =====================================================================
// kernel 1: y[b, o] = bias[o]
// =====================================================================
__global__ __launch_bounds__(256) void hyper_init(const float* __restrict__ bias,
                                                  float* __restrict__ y) {
    int i = blockIdx.x * 256 + threadIdx.x;
    y[i] = __ldg(bias + (i & (DIM - 1)));
}

// =====================================================================
// kernel 2: one warp per (b_half, k); lane = sample index a (0..31).
// 4 partitionable-threefry hashes per lane: (bh, r=0/1), (bh+8, r=0/1).
// Lanes 0..7 carry the 8 floor/ceil neighbors (lane>>2 = batch half,
// lane&3 = corner).
// =====================================================================
__global__ __launch_bounds__(256) void hyper_main(const float* __restrict__ x,
                                                  float*       __restrict__ y) {
    const int w    = blockIdx.x * 8 + (threadIdx.x >> 5);   // 0 .. 131071
    const int lane = threadIdx.x & 31;
    const int bh   = w >> 14;            // 0..7
    const int k    = w & (KTUP - 1);

    // ---- precomputed params (warp-uniform broadcast loads) ----
    const float4 p0 = __ldg(&g_params[bh * KTUP + k]);            // batch bh
    const float4 p1 = __ldg(&g_params[(bh + HALF_B) * KTUP + k]); // batch bh+8

    // ---- sampled integer tuples: flat element index in (B,K,ADD,RANK) ----
    const uint32_t e00 = (uint32_t)(w * (ADDS * 2) + lane * 2);
    int si0[2], si1[2];
    si0[0] = bits_to_idx(jax_random_bits32(e00));                 // (bh,   dim0)
    si1[0] = bits_to_idx(jax_random_bits32(e00 + 1u));            // (bh,   dim1)
    si0[1] = bits_to_idx(jax_random_bits32(e00 + 0x800000u));     // (bh+8, dim0)
    si1[1] = bits_to_idx(jax_random_bits32(e00 + 0x800001u));     // (bh+8, dim1)

    // ---- Gaussian props for samples ----
    float psamp[2];
    {
        float d0 = (float)si0[0] - p0.x;
        float d1 = (float)si1[0] - p0.y;
        psamp[0] = __expf(fmaf(d0, d0, d1 * d1) * p0.z);
        d0 = (float)si0[1] - p1.x;
        d1 = (float)si1[1] - p1.y;
        psamp[1] = __expf(fmaf(d0, d0, d1 * d1) * p1.z);
    }

    // ---- neighbors: lanes 0..7, one (batch, corner) each ----
    float pnb = 0.0f;
    int   ni0 = 0, ni1 = 0;
    if (lane < 8) {
        const float mm0 = (lane & 4) ? p1.x : p0.x;
        const float mm1 = (lane & 4) ? p1.y : p0.y;
        const float nhh = (lane & 4) ? p1.z : p0.z;
        float g0 = (lane & 2) ? ceilf(mm0) : floorf(mm0);
        float g1 = (lane & 1) ? ceilf(mm1) : floorf(mm1);
        ni0 = (int)g0;  ni1 = (int)g1;
        float d0 = g0 - mm0;
        float d1 = g1 - mm1;
        pnb = __expf(fmaf(d0, d0, d1 * d1) * nhh);
    }

    // ---- normalization: den = sum_p props + P*eps ----
    float s0 = psamp[0] + ((lane < 4)              ? pnb : 0.0f);
    float s1 = psamp[1] + ((lane >= 4 && lane < 8) ? pnb : 0.0f);
#pragma unroll
    for (int o = 16; o > 0; o >>= 1) {
        s0 += __shfl_xor_sync(0xffffffffu, s0, o);
        s1 += __shfl_xor_sync(0xffffffffu, s1, o);
    }
    const float sc0 = __fdividef(p0.w, s0 + (float)(NP) * 1e-6f);
    const float sc1 = __fdividef(p1.w, s1 + (float)(NP) * 1e-6f);

    // ---- gather / scatter-add ----
    const float* xr0 = x + (size_t)bh * DIM;
    const float* xr1 = x + (size_t)(bh + HALF_B) * DIM;
    float* yr0 = y + (size_t)bh * DIM;
    float* yr1 = y + (size_t)(bh + HALF_B) * DIM;

    atomicAdd(yr0 + si0[0], sc0 * psamp[0] * __ldg(xr0 + si1[0]));
    atomicAdd(yr1 + si0[1], sc1 * psamp[1] * __ldg(xr1 + si1[1]));
    if (lane < 8) {
        const float* xr = (lane & 4) ? xr1 : xr0;
        float*       yr = (lane & 4) ? yr1 : yr0;
        const float  sc = (lane & 4) ? sc1 : sc0;
        atomicAdd(yr + ni0, sc * pnb * __ldg(xr + ni1));
    }
}

// =====================================================================
extern "C" void kernel_launch(void* const* d_in, const int* in_sizes, int n_in,
                              void* d_out, int out_size) {
    const float*  x    = (const float*)d_in[0];          // (16, 65536)
    const float4* res4 = (const float4*)d_in[1];         // (16, 16384, 4)
    const float*  bias = (const float*)d_in[2];          // (65536,)
    // d_in[3] = temp_indices: fully overwritten by learn_cols -> unused
    float* y = (float*)d_out;                            // (16, 65536)

    hyper_params<<<(BATCH * KTUP) / 256, 256>>>(res4);
    hyper_init<<<(BATCH * DIM) / 256, 256>>>(bias, y);
    hyper_main<<<(HALF_B * KTUP) / 8, 256>>>(x, y);
}

// round 6
// speedup vs baseline: 1.1987x; 1.0319x over previous
#include <cuda_runtime.h>
#include <cstdint>
#include <math.h>

// ---- problem constants ----
#define BATCH    16
#define KTUP     16384
#define ADDS     32
#define NP       36          // 2^2 + 32 candidates per point
#define DIM      65536       // IN_DIM == OUT_DIM
#define HALF_B   8

// 4MB precomputed-parameter scratch: {m0, m1, nh, val} per (b, k)
__device__ float4 g_params[BATCH * KTUP];

// =====================================================================
// threefry-2x32, 20 rounds, exactly as jax._src.prng (key = (0, 42)).
// Partitionable mode: counter = (0, flat_index), bits = o0 ^ o1.
// =====================================================================
__device__ __forceinline__ void threefry2x32_42(uint32_t c0, uint32_t c1,
                                                uint32_t& o0, uint32_t& o1) {
    const uint32_t ks0 = 0u;
    const uint32_t ks1 = 42u;
    const uint32_t ks2 = 0x1BD11BDAu ^ 0u ^ 42u;
    uint32_t x0 = c0 + ks0;
    uint32_t x1 = c1 + ks1;
#define TF_R(rot) { x0 += x1; x1 = __funnelshift_l(x1, x1, rot); x1 ^= x0; }
    TF_R(13) TF_R(15) TF_R(26) TF_R(6)   x0 += ks1; x1 += ks2 + 1u;
    TF_R(17) TF_R(29) TF_R(16) TF_R(24)  x0 += ks2; x1 += ks0 + 2u;
    TF_R(13) TF_R(15) TF_R(26) TF_R(6)   x0 += ks0; x1 += ks1 + 3u;
    TF_R(17) TF_R(29) TF_R(16) TF_R(24)  x0 += ks1; x1 += ks2 + 4u;
    TF_R(13) TF_R(15) TF_R(26) TF_R(6)   x0 += ks2; x1 += ks0 + 5u;
#undef TF_R
    o0 = x0; o1 = x1;
}

__device__ __forceinline__ uint32_t jax_random_bits32(uint32_t e) {
    uint32_t o0, o1;
    threefry2x32_42(0u, e, o0, o1);
    return o0 ^ o1;
}

// bits -> uniform [0,1) -> *(1-1e-6) -> *65536 -> floor -> int32, bit-exact vs JAX
__device__ __forceinline__ int bits_to_idx(uint32_t bits) {
    float u = __uint_as_float((bits >> 9) | 0x3f800000u) - 1.0f;
    const float OME = (float)(1.0 - 1e-6);   // fl32(0.999999)
    float t = __fmul_rn(__fmul_rn(u, OME), 65536.0f);
    return (int)t;                           // trunc == floor, t >= 0
}

// ---- sigmoid / softplus: IDENTICAL arithmetic to passing rounds 4/5 ----
__device__ __forceinline__ float xla_sigmoid(float v) {
    float e = expf(-v);                      // accurate expf
    return __fdiv_rn(1.0f, __fadd_rn(1.0f, e));
}
__device__ __forceinline__ float softplus_f(float v) {
    return fmaxf(v, 0.0f) + log1pf(__expf(-fabsf(v)));
}

// =====================================================================
// prolog: blocks [0, 1024)   -> per-(b,k) parameter precompute
//         blocks [1024, 2048) -> y[b, o] = bias[o]  (float4)
// Fusing overlaps the latency-bound MUFU/div chains with the DRAM-bound
// broadcast and saves a launch.
// =====================================================================
__global__ __launch_bounds__(256) void hyper_prolog(const float4* __restrict__ res4,
                                                    const float4* __restrict__ bias4,
                                                    float4*       __restrict__ y4) {
    const int b = blockIdx.x;
    const int t = threadIdx.x;
    if (b < (BATCH * KTUP) / 256) {
        int i = b * 256 + t;                         // 0 .. BATCH*KTUP-1
        float4 r = __ldg(&res4[i]);
        float4 p;
        p.x = __fmul_rn(xla_sigmoid(r.x), 65535.0f); // m0
        p.y = __fmul_rn(xla_sigmoid(r.y), 65535.0f); // m1
        float sg = (softplus_f(r.z + 2.0f) + 1e-6f) * 65536.0f;
        p.z = -0.5f / (sg * sg);                     // nh
        p.w = r.w;                                   // val
        g_params[i] = p;
    } else {
        int i = (b - (BATCH * KTUP) / 256) * 256 + t;   // float4 element index
        y4[i] = __ldg(&bias4[i & (DIM / 4 - 1)]);
    }
}

// =====================================================================
// main: one warp per (b_half, k); lane = sample index a (0..31).
// 4 partitionable-threefry hashes per lane: (bh, r=0/1), (bh+8, r=0/1).
// Lanes 0..3 carry the 8 floor/ceil neighbors merged by out-row:
//   lane = 2*batch_half_sel + (floor/ceil of m0); each lane owns 2 corners
//   sharing one out index -> 2 gathers + 1 atomic.
// =====================================================================
__global__ __launch_bounds__(256) void hyper_main(const float* __restrict__ x,
                                                  float*       __restrict__ y) {
    const int w    = blockIdx.x * 8 + (threadIdx.x >> 5);   // 0 .. 131071
    const int lane = threadIdx.x & 31;
    const int bh   = w >> 14;            // 0..7
    const int k    = w & (KTUP - 1);

    // ---- precomputed params (warp-uniform broadcast loads) ----
    const float4 p0 = __ldg(&g_params[bh * KTUP + k]);            // batch bh
    const float4 p1 = __ldg(&g_params[(bh + HALF_B) * KTUP + k]); // batch bh+8

    // ---- sampled integer tuples: flat element index in (B,K,ADD,RANK) ----
    const uint32_t e00 = (uint32_t)(w * (ADDS * 2) + lane * 2);
    int si0[2], si1[2];
    si0[0] = bits_to_idx(jax_random_bits32(e00));                 // (bh,   dim0)
    si1[0] = bits_to_idx(jax_random_bits32(e00 + 1u));            // (bh,   dim1)
    si0[1] = bits_to_idx(jax_random_bits32(e00 + 0x800000u));     // (bh+8, dim0)
    si1[1] = bits_to_idx(jax_random_bits32(e00 + 0x800001u));     // (bh+8, dim1)

    // ---- Gaussian props for samples ----
    float psamp[2];
    {
        float d0 = (float)si0[0] - p0.x;
        float d1 = (float)si1[0] - p0.y;
        psamp[0] = __expf(fmaf(d0, d0, d1 * d1) * p0.z);
        d0 = (float)si0[1] - p1.x;
        d1 = (float)si1[1] - p1.y;
        psamp[1] = __expf(fmaf(d0, d0, d1 * d1) * p1.z);
    }

    // ---- neighbors: lanes 0..3, two corners (one out-row) each ----
    float pa = 0.0f, pb = 0.0f;
    int   ng0 = 0, nf1 = 0, nc1 = 0;
    if (lane < 4) {
        const bool hb  = lane >= 2;                 // batch-half select
        const float mm0 = hb ? p1.x : p0.x;
        const float mm1 = hb ? p1.y : p0.y;
        const float nhh = hb ? p1.z : p0.z;
        float g0  = (lane & 1) ? ceilf(mm0) : floorf(mm0);
        float f1v = floorf(mm1), c1v = ceilf(mm1);
        ng0 = (int)g0;  nf1 = (int)f1v;  nc1 = (int)c1v;
        float d0 = g0 - mm0;
        float df = f1v - mm1, dc = c1v - mm1;
        pa = __expf(fmaf(d0, d0, df * df) * nhh);   // corner (g0, f1)
        pb = __expf(fmaf(d0, d0, dc * dc) * nhh);   // corner (g0, c1)
    }

    // ---- normalization: den = sum_p props + P*eps ----
    float s0 = psamp[0] + ((lane < 2)               ? pa + pb : 0.0f);
    float s1 = psamp[1] + ((lane >= 2 && lane < 4)  ? pa + pb : 0.0f);
#pragma unroll
    for (int o = 16; o > 0; o >>= 1) {
        s0 += __shfl_xor_sync(0xffffffffu, s0, o);
        s1 += __shfl_xor_sync(0xffffffffu, s1, o);
    }
    const float sc0 = __fdividef(p0.w, s0 + (float)(NP) * 1e-6f);
    const float sc1 = __fdividef(p1.w, s1 + (float)(NP) * 1e-6f);

    // ---- gather / scatter-add ----
    const float* xr0 = x + (size_t)bh * DIM;
    const float* xr1 = x + (size_t)(bh + HALF_B) * DIM;
    float* yr0 = y + (size_t)bh * DIM;
    float* yr1 = y + (size_t)(bh + HALF_B) * DIM;

    atomicAdd(yr0 + si0[0], sc0 * psamp[0] * __ldg(xr0 + si1[0]));
    atomicAdd(yr1 + si0[1], sc1 * psamp[1] * __ldg(xr1 + si1[1]));
    if (lane < 4) {
        const bool hb = lane >= 2;
        const float* xr = hb ? xr1 : xr0;
        float*       yr = hb ? yr1 : yr0;
        const float  sc = hb ? sc1 : sc0;
        float contrib = sc * fmaf(pa, __ldg(xr + nf1), pb * __ldg(xr + nc1));
        atomicAdd(yr + ng0, contrib);
    }
}

// =====================================================================
extern "C" void kernel_launch(void* const* d_in, const int* in_sizes, int n_in,
                              void* d_out, int out_size) {
    const float*  x     = (const float*)d_in[0];          // (16, 65536)
    const float4* res4  = (const float4*)d_in[1];         // (16, 16384, 4)
    const float4* bias4 = (const float4*)d_in[2];         // (65536,)
    // d_in[3] = temp_indices: fully overwritten by learn_cols -> unused
    float* y = (float*)d_out;                             // (16, 65536)

    const int nb_params = (BATCH * KTUP) / 256;           // 1024
    const int nb_init   = (BATCH * DIM / 4) / 256;        // 1024
    hyper_prolog<<<nb_params + nb_init, 256>>>(res4, bias4, (float4*)y);
    hyper_main<<<(HALF_B * KTUP) / 8, 256>>>(x, y);
}